// round 10
// baseline (speedup 1.0000x reference)
#include <cuda_runtime.h>
#include <cstdint>

// Problem dims (fixed)
#define ZD 16
#define YD 384
#define XD 384
#define YP 386        // padded y rows in E/ZC (row 0 and 385 stay zero)
#define NWIN_I 17     // z-pairs
#define NWIN_Y 385    // window rows
#define NGX 24        // 16-window groups; group 23 also does edge window x=384
#define TOTAL_B_THREADS (NWIN_I * NWIN_Y * NGX)          // 157080
#define K2_BLK 128
#define B_BLOCKS ((TOTAL_B_THREADS + K2_BLK - 1) / K2_BLK)   // 1228
#define NP_WIN 148225.0                                   // 385*385
#define SLAB (YD * XD)                                    // 147456

// Scratch (static __device__ — zero-initialized; padded rows never written)
__device__ float         g_E[NWIN_I * YP * XD];   // z-pair sums of (s-l)^2
__device__ unsigned char g_ZC[NWIN_I * YP * XD];  // z-pair code: l0@0,l1@2,p0@4,p1@6
__device__ float         g_part[3 * B_BLOCKS];
__device__ unsigned      g_count;

// ---------------------------------------------------------------------------
// k1: z-pass. One thread per (y,x) column; walks z, emits 17 z-pair sums+codes.
__global__ void k1(const float* __restrict__ pred, const int* __restrict__ lab) {
    int x = threadIdx.x;
    int y = blockIdx.x;
    if (x == 0 && y == 0) g_count = 0u;
    int base = y * XD + x;
    int obase = (y + 1) * XD + x;   // padded row index

    float dprev = 0.f;
    unsigned cprev = 0u;
#pragma unroll 4
    for (int z = 0; z < ZD; z++) {
        float p = __ldg(&pred[z * SLAB + base]);
        int   l = __ldg(&lab[z * SLAB + base]);
        float s = __fdividef(1.f, 1.f + __expf(-p));
        float f = (float)l;
        float d = (s - f) * (s - f);
        unsigned c = (unsigned)(l & 1) | (p > 0.f ? 0x10u : 0u);  // lab@0, pred@4
        g_E[z * (YP * XD) + obase]  = dprev + d;
        g_ZC[z * (YP * XD) + obase] = (unsigned char)(cprev | (c << 2));
        dprev = d;
        cprev = c;
    }
    g_E[ZD * (YP * XD) + obase]  = dprev;
    g_ZC[ZD * (YP * XD) + obase] = (unsigned char)cprev;
}

// ---------------------------------------------------------------------------
// Rare-path BCE: byte==0 -> softplus(p), byte==255 -> softplus(-p).
__device__ __noinline__ float bce8(const float* __restrict__ pred, int i, int yw, int x, bool ones) {
    float s = 0.f;
#pragma unroll
    for (int dz = 0; dz < 2; dz++)
#pragma unroll
        for (int dy = 0; dy < 2; dy++)
#pragma unroll
            for (int dx = 0; dx < 2; dx++) {
                int z = i - 1 + dz, y = yw - 1 + dy, xv = x - 1 + dx;
                if (z >= 0 && z < ZD && y >= 0 && y < YD && xv >= 0 && xv < XD) {
                    float p = __ldg(&pred[(z * YD + y) * XD + xv]);
                    float u = ones ? -p : p;
                    s += fmaxf(u, 0.f) + __logf(1.f + __expf(-fabsf(u)));
                }
            }
    return s;
}

__device__ __forceinline__ float warp_sum(float v) {
#pragma unroll
    for (int off = 16; off > 0; off >>= 1)
        v += __shfl_down_sync(0xffffffffu, v, off);
    return v;
}

__device__ __forceinline__ unsigned wsel(uint4 u, int j) {
    return j == 0 ? u.x : (j == 1 ? u.y : (j == 2 ? u.z : u.w));
}

// ---------------------------------------------------------------------------
// k2: each thread sweeps 16 consecutive windows along x for a fixed (i, yw).
// All loads for the strip are hoisted up-front (single latency round, MLP~11).
// 128-thread blocks, 9 CTAs/SM -> 1228 blocks fit one wave (capacity 1332).
__global__ void __launch_bounds__(K2_BLK, 9)
k2(const float* __restrict__ pred, const float* __restrict__ area,
   float* __restrict__ out) {
    __shared__ float a_sh[256];
    __shared__ float wN[4], wD[4], wB[4];
    __shared__ bool is_last;
    int tid = threadIdx.x;

    // permuted area LUT: index = (leftcol_nibble<<4)|rightcol_nibble,
    // nibble bit m = dz*2+dy -> true byte bit 2m+dx (left dx=0, right dx=1)
#pragma unroll
    for (int rep = 0; rep < 2; rep++) {
        int idx = tid + rep * K2_BLK;
        int a = idx >> 4, b = idx & 15;
        int byte = 0;
#pragma unroll
        for (int m = 0; m < 4; m++) {
            byte |= ((a >> m) & 1) << (2 * m);
            byte |= ((b >> m) & 1) << (2 * m + 1);
        }
        a_sh[idx] = __ldg(&area[byte]);
    }
    __syncthreads();

    float S1 = 0.f, S2 = 0.f, Sq = 0.f, accB = 0.f;
    int t = blockIdx.x * K2_BLK + tid;
    if (t < TOTAL_B_THREADS) {
        int g = t % NGX;
        int rem = t / NGX;
        int yw = rem % NWIN_Y;
        int i = rem / NWIN_Y;
        int x0 = g * 16;

        int rA = (i * YP + yw) * XD;
        int rB = rA + XD;

        // ---- hoisted load round: all 16 columns + carry, MLP ~ 11 ----
        const float4* pA = reinterpret_cast<const float4*>(g_E + rA + x0);
        const float4* pB = reinterpret_cast<const float4*>(g_E + rB + x0);
        float4 a0 = pA[0], a1 = pA[1], a2 = pA[2], a3 = pA[3];
        float4 b0 = pB[0], b1 = pB[1], b2 = pB[2], b3 = pB[3];
        uint4 zA = *reinterpret_cast<const uint4*>(g_ZC + rA + x0);
        uint4 zB = *reinterpret_cast<const uint4*>(g_ZC + rB + x0);

        float Fp;
        unsigned cbp;
        if (x0 == 0) {
            Fp = 0.f;
            cbp = 0u;
        } else {
            int c = x0 - 1;
            float eAc = g_E[rA + c];
            float eBc = g_E[rB + c];
            unsigned zAc = g_ZC[rA + c];
            unsigned zBc = g_ZC[rB + c];
            Fp = eAc + eBc;
            cbp = zAc | (zBc << 1);
        }

#pragma unroll
        for (int j = 0; j < 4; j++) {
            float4 ea = j == 0 ? a0 : (j == 1 ? a1 : (j == 2 ? a2 : a3));
            float4 eb = j == 0 ? b0 : (j == 1 ? b1 : (j == 2 ? b2 : b3));
            // column codes for 4 columns: zc bytes <= 0x55 -> <<1 stays in-lane
            unsigned cw = wsel(zA, j) | (wsel(zB, j) << 1);
            // prevw byte k = code of column k-1 (byte0 = carry)
            unsigned prevw = __byte_perm(cw, cbp, 0x2104);
            // L byte k = lidx of window k ; P byte k = pidx of window k
            unsigned L = ((prevw << 4) & 0xF0F0F0F0u) | (cw & 0x0F0F0F0Fu);
            unsigned P = (prevw & 0xF0F0F0F0u) | ((cw >> 4) & 0x0F0F0F0Fu);

            float F0 = ea.x + eb.x;
            float F1 = ea.y + eb.y;
            float F2 = ea.z + eb.z;
            float F3 = ea.w + eb.w;

            float q0 = Fp + F0;
            float q1 = F0 + F1;
            float q2 = F1 + F2;
            float q3 = F2 + F3;

            float la0 = a_sh[L & 0xFFu];
            float la1 = a_sh[(L >> 8) & 0xFFu];
            float la2 = a_sh[(L >> 16) & 0xFFu];
            float la3 = a_sh[L >> 24];
            float pa0 = a_sh[P & 0xFFu];
            float pa1 = a_sh[(P >> 8) & 0xFFu];
            float pa2 = a_sh[(P >> 16) & 0xFFu];
            float pa3 = a_sh[P >> 24];

            Sq = fmaf(q0, la0, Sq);
            Sq = fmaf(q1, la1, Sq);
            Sq = fmaf(q2, la2, Sq);
            Sq = fmaf(q3, la3, Sq);
            S1 += (la0 + la1) + (la2 + la3);
            S2 += (pa0 + pa1) + (pa2 + pa3);

            // rare path: any window with label byte 0 or 255
            unsigned r = __vcmpeq4(L, 0u) | __vcmpeq4(L, 0xFFFFFFFFu);
            if (r) {
#pragma unroll
                for (int k = 0; k < 4; k++) {
                    unsigned lb = (L >> (8 * k)) & 0xFFu;
                    if (lb == 0u || lb == 255u)
                        accB += bce8(pred, i, yw, x0 + 4 * j + k, lb == 255u);
                }
            }

            Fp = F3;
            cbp = cw >> 24;
        }

        // group 23: edge window x=384 (right column is zero padding)
        if (g == NGX - 1) {
            float q = Fp;
            unsigned lidx = (cbp << 4) & 0xF0u;
            unsigned pidx = cbp & 0xF0u;
            float la = a_sh[lidx];
            float pa = a_sh[pidx];
            Sq = fmaf(q, la, Sq);
            S1 += la;
            S2 += pa;
            if (lidx == 0u)   // lidx==255 impossible here (low nibble is 0)
                accB += bce8(pred, i, yw, 384, false);
        }
    }
    float accN = fmaf(Sq, -0.125f, S1);   // sum of (1 - q/8)*la
    float accD = S1 + S2;

    // deterministic warp-shuffle reduction (4 warps)
    accN = warp_sum(accN);
    accD = warp_sum(accD);
    accB = warp_sum(accB);
    int lane = tid & 31, warp = tid >> 5;
    if (lane == 0) { wN[warp] = accN; wD[warp] = accD; wB[warp] = accB; }
    __syncthreads();
    if (warp == 0) {
        float vN = lane < 4 ? wN[lane] : 0.f;
        float vD = lane < 4 ? wD[lane] : 0.f;
        float vB = lane < 4 ? wB[lane] : 0.f;
#pragma unroll
        for (int off = 2; off > 0; off >>= 1) {
            vN += __shfl_down_sync(0xffffffffu, vN, off);
            vD += __shfl_down_sync(0xffffffffu, vD, off);
            vB += __shfl_down_sync(0xffffffffu, vB, off);
        }
        if (lane == 0) {
            g_part[3 * blockIdx.x + 0] = vN;
            g_part[3 * blockIdx.x + 1] = vD;
            g_part[3 * blockIdx.x + 2] = vB;
        }
    }

    __threadfence();
    if (tid == 0) {
        unsigned prev = atomicAdd(&g_count, 1u);
        is_last = (prev == B_BLOCKS - 1);
    }
    __syncthreads();
    if (!is_last) return;

    double sN = 0.0, sD = 0.0, sB = 0.0;
    for (int b = tid; b < B_BLOCKS; b += K2_BLK) {
        sN += (double)g_part[3 * b + 0];
        sD += (double)g_part[3 * b + 1];
        sB += (double)g_part[3 * b + 2];
    }
    __shared__ double rd[K2_BLK];
    rd[tid] = sN; __syncthreads();
    for (int s = K2_BLK / 2; s > 0; s >>= 1) { if (tid < s) rd[tid] += rd[tid + s]; __syncthreads(); }
    double tN = rd[0]; __syncthreads();
    rd[tid] = sD; __syncthreads();
    for (int s = K2_BLK / 2; s > 0; s >>= 1) { if (tid < s) rd[tid] += rd[tid + s]; __syncthreads(); }
    double tD = rd[0]; __syncthreads();
    rd[tid] = sB; __syncthreads();
    for (int s = K2_BLK / 2; s > 0; s >>= 1) { if (tid < s) rd[tid] += rd[tid + s]; __syncthreads(); }
    double tB = rd[0];

    if (tid == 0) {
        double dice = 1.0 - (2.0 * tN + 1e-3) / (tD + 1e-3);
        double vol = tB / (8.0 * NP_WIN);
        out[0] = (float)(dice + vol);
    }
}

// ---------------------------------------------------------------------------
extern "C" void kernel_launch(void* const* d_in, const int* in_sizes, int n_in,
                              void* d_out, int out_size) {
    const float* pred   = (const float*)d_in[0];
    const int*   labels = (const int*)d_in[1];
    const float* area   = (const float*)d_in[2];

    k1<<<YD, XD>>>(pred, labels);
    k2<<<B_BLOCKS, K2_BLK>>>(pred, area, (float*)d_out);
}

// round 11
// speedup vs baseline: 1.0981x; 1.0981x over previous
#include <cuda_runtime.h>
#include <cstdint>

// Problem dims (fixed)
#define ZD 16
#define YD 384
#define XD 384
#define YP 386        // padded y rows in E/ZC (row 0 and 385 stay zero)
#define NWIN_I 17     // z-pairs
#define NWIN_Y 385    // window rows
#define NGX 48        // 8-window groups; group 47 also does edge window x=384
#define TOTAL_B_THREADS (NWIN_I * NWIN_Y * NGX)          // 314160
#define K2_BLK 256
#define B_BLOCKS ((TOTAL_B_THREADS + K2_BLK - 1) / K2_BLK)   // 1228
#define NP_WIN 148225.0                                   // 385*385
#define SLAB (YD * XD)                                    // 147456

// Scratch (static __device__ — zero-initialized; padded rows never written)
__device__ float         g_E[NWIN_I * YP * XD];   // z-pair sums of (s-l)^2
__device__ unsigned char g_ZC[NWIN_I * YP * XD];  // z-pair code: l0@0,l1@2,p0@4,p1@6
__device__ float         g_part[3 * B_BLOCKS];
__device__ unsigned      g_count;

// ---------------------------------------------------------------------------
// k1: z-pass. One thread per (y,x) column; walks z, emits 17 z-pair sums+codes.
__global__ void k1(const float* __restrict__ pred, const int* __restrict__ lab) {
    int x = threadIdx.x;
    int y = blockIdx.x;
    if (x == 0 && y == 0) g_count = 0u;
    int base = y * XD + x;
    int obase = (y + 1) * XD + x;   // padded row index

    float dprev = 0.f;
    unsigned cprev = 0u;
#pragma unroll 4
    for (int z = 0; z < ZD; z++) {
        float p = __ldg(&pred[z * SLAB + base]);
        int   l = __ldg(&lab[z * SLAB + base]);
        float s = __fdividef(1.f, 1.f + __expf(-p));
        float f = (float)l;
        float d = (s - f) * (s - f);
        unsigned c = (unsigned)(l & 1) | (p > 0.f ? 0x10u : 0u);  // lab@0, pred@4
        g_E[z * (YP * XD) + obase]  = dprev + d;
        g_ZC[z * (YP * XD) + obase] = (unsigned char)(cprev | (c << 2));
        dprev = d;
        cprev = c;
    }
    g_E[ZD * (YP * XD) + obase]  = dprev;
    g_ZC[ZD * (YP * XD) + obase] = (unsigned char)cprev;
}

// ---------------------------------------------------------------------------
// Rare-path BCE: byte==0 -> softplus(p), byte==255 -> softplus(-p).
__device__ __noinline__ float bce8(const float* __restrict__ pred, int i, int yw, int x, bool ones) {
    float s = 0.f;
#pragma unroll
    for (int dz = 0; dz < 2; dz++)
#pragma unroll
        for (int dy = 0; dy < 2; dy++)
#pragma unroll
            for (int dx = 0; dx < 2; dx++) {
                int z = i - 1 + dz, y = yw - 1 + dy, xv = x - 1 + dx;
                if (z >= 0 && z < ZD && y >= 0 && y < YD && xv >= 0 && xv < XD) {
                    float p = __ldg(&pred[(z * YD + y) * XD + xv]);
                    float u = ones ? -p : p;
                    s += fmaxf(u, 0.f) + __logf(1.f + __expf(-fabsf(u)));
                }
            }
    return s;
}

__device__ __forceinline__ float warp_sum(float v) {
#pragma unroll
    for (int off = 16; off > 0; off >>= 1)
        v += __shfl_down_sync(0xffffffffu, v, off);
    return v;
}

// ---------------------------------------------------------------------------
// k2: each thread sweeps 8 consecutive windows along x for a fixed (i, yw).
// Group 47 also handles the x=384 edge window (zero right column).
// 1228 blocks @ 8 CTAs/SM (32-reg target) -> ~1.04 waves, occ up to 100%.
__global__ void __launch_bounds__(K2_BLK, 8)
k2(const float* __restrict__ pred, const float* __restrict__ area,
   float* __restrict__ out) {
    __shared__ float a_sh[256];
    __shared__ float wN[8], wD[8], wB[8];
    __shared__ bool is_last;
    int tid = threadIdx.x;

    // permuted area LUT: index = (leftcol_nibble<<4)|rightcol_nibble,
    // nibble bit m = dz*2+dy -> true byte bit 2m+dx (left dx=0, right dx=1)
    {
        int a = tid >> 4, b = tid & 15;
        int byte = 0;
#pragma unroll
        for (int m = 0; m < 4; m++) {
            byte |= ((a >> m) & 1) << (2 * m);
            byte |= ((b >> m) & 1) << (2 * m + 1);
        }
        a_sh[tid] = __ldg(&area[byte]);
    }
    __syncthreads();

    float S1 = 0.f, S2 = 0.f, Sq = 0.f, accB = 0.f;
    int t = blockIdx.x * K2_BLK + tid;
    if (t < TOTAL_B_THREADS) {
        int g = t % NGX;
        int rem = t / NGX;
        int yw = rem % NWIN_Y;
        int i = rem / NWIN_Y;
        int x0 = g * 8;

        int rA = (i * YP + yw) * XD;
        int rB = rA + XD;

        // ---- one load round: 8 columns (2 float4/row) + codes + carry ----
        const float4* pA = reinterpret_cast<const float4*>(g_E + rA + x0);
        const float4* pB = reinterpret_cast<const float4*>(g_E + rB + x0);
        float4 a0 = pA[0], a1 = pA[1];
        float4 b0 = pB[0], b1 = pB[1];
        uint2 za = *reinterpret_cast<const uint2*>(g_ZC + rA + x0);
        uint2 zb = *reinterpret_cast<const uint2*>(g_ZC + rB + x0);

        float Fp;
        unsigned cbp;
        if (x0 == 0) {
            Fp = 0.f;
            cbp = 0u;
        } else {
            int c = x0 - 1;
            float eAc = g_E[rA + c];
            float eBc = g_E[rB + c];
            unsigned zAc = g_ZC[rA + c];
            unsigned zBc = g_ZC[rB + c];
            Fp = eAc + eBc;
            cbp = zAc | (zBc << 1);
        }

#pragma unroll
        for (int j = 0; j < 2; j++) {
            float4 ea = j ? a1 : a0;
            float4 eb = j ? b1 : b0;
            // column codes for 4 columns: zc bytes <= 0x55 -> <<1 stays in-lane
            unsigned cw = (j ? za.y : za.x) | ((j ? zb.y : zb.x) << 1);
            // prevw byte k = code of column k-1 (byte0 = carry)
            unsigned prevw = __byte_perm(cw, cbp, 0x2104);
            // L byte k = lidx of window k ; P byte k = pidx of window k
            unsigned L = ((prevw << 4) & 0xF0F0F0F0u) | (cw & 0x0F0F0F0Fu);
            unsigned P = (prevw & 0xF0F0F0F0u) | ((cw >> 4) & 0x0F0F0F0Fu);

            float F0 = ea.x + eb.x;
            float F1 = ea.y + eb.y;
            float F2 = ea.z + eb.z;
            float F3 = ea.w + eb.w;

            float q0 = Fp + F0;
            float q1 = F0 + F1;
            float q2 = F1 + F2;
            float q3 = F2 + F3;

            float la0 = a_sh[L & 0xFFu];
            float la1 = a_sh[(L >> 8) & 0xFFu];
            float la2 = a_sh[(L >> 16) & 0xFFu];
            float la3 = a_sh[L >> 24];
            float pa0 = a_sh[P & 0xFFu];
            float pa1 = a_sh[(P >> 8) & 0xFFu];
            float pa2 = a_sh[(P >> 16) & 0xFFu];
            float pa3 = a_sh[P >> 24];

            Sq = fmaf(q0, la0, Sq);
            Sq = fmaf(q1, la1, Sq);
            Sq = fmaf(q2, la2, Sq);
            Sq = fmaf(q3, la3, Sq);
            S1 += (la0 + la1) + (la2 + la3);
            S2 += (pa0 + pa1) + (pa2 + pa3);

            // rare path: any window with label byte 0 or 255
            unsigned r = __vcmpeq4(L, 0u) | __vcmpeq4(L, 0xFFFFFFFFu);
            if (r) {
#pragma unroll
                for (int k = 0; k < 4; k++) {
                    unsigned lb = (L >> (8 * k)) & 0xFFu;
                    if (lb == 0u || lb == 255u)
                        accB += bce8(pred, i, yw, x0 + 4 * j + k, lb == 255u);
                }
            }

            Fp = F3;
            cbp = cw >> 24;
        }

        // group 47: edge window x=384 (right column is zero padding)
        if (g == NGX - 1) {
            float q = Fp;
            unsigned lidx = (cbp << 4) & 0xF0u;
            unsigned pidx = cbp & 0xF0u;
            float la = a_sh[lidx];
            float pa = a_sh[pidx];
            Sq = fmaf(q, la, Sq);
            S1 += la;
            S2 += pa;
            if (lidx == 0u)   // lidx==255 impossible here (low nibble is 0)
                accB += bce8(pred, i, yw, 384, false);
        }
    }
    float accN = fmaf(Sq, -0.125f, S1);   // sum of (1 - q/8)*la
    float accD = S1 + S2;

    // deterministic warp-shuffle reduction
    accN = warp_sum(accN);
    accD = warp_sum(accD);
    accB = warp_sum(accB);
    int lane = tid & 31, warp = tid >> 5;
    if (lane == 0) { wN[warp] = accN; wD[warp] = accD; wB[warp] = accB; }
    __syncthreads();
    if (warp == 0) {
        float vN = lane < 8 ? wN[lane] : 0.f;
        float vD = lane < 8 ? wD[lane] : 0.f;
        float vB = lane < 8 ? wB[lane] : 0.f;
#pragma unroll
        for (int off = 4; off > 0; off >>= 1) {
            vN += __shfl_down_sync(0xffffffffu, vN, off);
            vD += __shfl_down_sync(0xffffffffu, vD, off);
            vB += __shfl_down_sync(0xffffffffu, vB, off);
        }
        if (lane == 0) {
            g_part[3 * blockIdx.x + 0] = vN;
            g_part[3 * blockIdx.x + 1] = vD;
            g_part[3 * blockIdx.x + 2] = vB;
        }
    }

    __threadfence();
    if (tid == 0) {
        unsigned prev = atomicAdd(&g_count, 1u);
        is_last = (prev == B_BLOCKS - 1);
    }
    __syncthreads();
    if (!is_last) return;

    double sN = 0.0, sD = 0.0, sB = 0.0;
    for (int b = tid; b < B_BLOCKS; b += K2_BLK) {
        sN += (double)g_part[3 * b + 0];
        sD += (double)g_part[3 * b + 1];
        sB += (double)g_part[3 * b + 2];
    }
    __shared__ double rd[K2_BLK];
    rd[tid] = sN; __syncthreads();
    for (int s = K2_BLK / 2; s > 0; s >>= 1) { if (tid < s) rd[tid] += rd[tid + s]; __syncthreads(); }
    double tN = rd[0]; __syncthreads();
    rd[tid] = sD; __syncthreads();
    for (int s = K2_BLK / 2; s > 0; s >>= 1) { if (tid < s) rd[tid] += rd[tid + s]; __syncthreads(); }
    double tD = rd[0]; __syncthreads();
    rd[tid] = sB; __syncthreads();
    for (int s = K2_BLK / 2; s > 0; s >>= 1) { if (tid < s) rd[tid] += rd[tid + s]; __syncthreads(); }
    double tB = rd[0];

    if (tid == 0) {
        double dice = 1.0 - (2.0 * tN + 1e-3) / (tD + 1e-3);
        double vol = tB / (8.0 * NP_WIN);
        out[0] = (float)(dice + vol);
    }
}

// ---------------------------------------------------------------------------
extern "C" void kernel_launch(void* const* d_in, const int* in_sizes, int n_in,
                              void* d_out, int out_size) {
    const float* pred   = (const float*)d_in[0];
    const int*   labels = (const int*)d_in[1];
    const float* area   = (const float*)d_in[2];

    k1<<<YD, XD>>>(pred, labels);
    k2<<<B_BLOCKS, K2_BLK>>>(pred, area, (float*)d_out);
}

// round 12
// speedup vs baseline: 1.3246x; 1.2063x over previous
#include <cuda_runtime.h>
#include <cstdint>

// Problem dims (fixed)
#define ZD 16
#define YD 384
#define XD 384
#define YP 386        // padded y rows (row 0 and 385 stay zero)
#define NWIN_I 17     // z-pairs
#define NWIN_Y 385    // window rows
#define NGX 48        // 8-window groups; group 47 also does edge window x=384
#define TOTAL_B_THREADS (NWIN_I * NWIN_Y * NGX)          // 314160
#define K2_BLK 256
#define B_BLOCKS ((TOTAL_B_THREADS + K2_BLK - 1) / K2_BLK)   // 1228
#define NP_WIN 148225.0                                   // 385*385
#define SLAB (YD * XD)                                    // 147456

// Scratch (static __device__ — zero-initialized; padded rows never written)
__device__ float         g_E[NWIN_I * YP * XD];   // z-pair sums of (s-l)^2
__device__ unsigned char g_ZC[NWIN_I * YP * XD];  // z-pair code: l0@0,l1@2,p0@4,p1@6
__device__ float2        g_S[NWIN_I * YP * XD];   // z-pair sums of (softplus(p), softplus(-p))
__device__ float         g_part[3 * B_BLOCKS];
__device__ unsigned      g_count;

// ---------------------------------------------------------------------------
// k1: z-pass. One thread per (y,x) column; walks z, emits 17 z-pair
// (E, code, softplus-pair) records.
__global__ void k1(const float* __restrict__ pred, const int* __restrict__ lab) {
    int x = threadIdx.x;
    int y = blockIdx.x;
    if (x == 0 && y == 0) g_count = 0u;
    int base = y * XD + x;
    int obase = (y + 1) * XD + x;   // padded row index

    float dprev = 0.f, spPrev = 0.f, snPrev = 0.f;
    unsigned cprev = 0u;
#pragma unroll 4
    for (int z = 0; z < ZD; z++) {
        float p = __ldg(&pred[z * SLAB + base]);
        int   l = __ldg(&lab[z * SLAB + base]);
        float s = __fdividef(1.f, 1.f + __expf(-p));
        float f = (float)l;
        float d = (s - f) * (s - f);
        float sp = fmaxf(p, 0.f) + __logf(1.f + __expf(-fabsf(p)));  // softplus(p)
        float sn = sp - p;                                           // softplus(-p)
        unsigned c = (unsigned)(l & 1) | (p > 0.f ? 0x10u : 0u);  // lab@0, pred@4
        int o = z * (YP * XD) + obase;
        g_E[o]  = dprev + d;
        g_ZC[o] = (unsigned char)(cprev | (c << 2));
        g_S[o]  = make_float2(spPrev + sp, snPrev + sn);
        dprev = d; spPrev = sp; snPrev = sn;
        cprev = c;
    }
    int o = ZD * (YP * XD) + obase;
    g_E[o]  = dprev;
    g_ZC[o] = (unsigned char)cprev;
    g_S[o]  = make_float2(spPrev, snPrev);
}

// ---------------------------------------------------------------------------
__device__ __forceinline__ float warp_sum(float v) {
#pragma unroll
    for (int off = 16; off > 0; off >>= 1)
        v += __shfl_down_sync(0xffffffffu, v, off);
    return v;
}

// ---------------------------------------------------------------------------
// k2: each thread sweeps 8 consecutive windows along x for a fixed (i, yw).
// Group 47 also handles the x=384 edge window (zero right column).
// Rare BCE path is 2-4 float2 loads of precomputed softplus pair-sums.
__global__ void __launch_bounds__(K2_BLK, 8)
k2(const float* __restrict__ pred, const float* __restrict__ area,
   float* __restrict__ out) {
    __shared__ float a_sh[256];
    __shared__ float wN[8], wD[8], wB[8];
    __shared__ bool is_last;
    int tid = threadIdx.x;

    // permuted area LUT: index = (leftcol_nibble<<4)|rightcol_nibble,
    // nibble bit m = dz*2+dy -> true byte bit 2m+dx (left dx=0, right dx=1)
    {
        int a = tid >> 4, b = tid & 15;
        int byte = 0;
#pragma unroll
        for (int m = 0; m < 4; m++) {
            byte |= ((a >> m) & 1) << (2 * m);
            byte |= ((b >> m) & 1) << (2 * m + 1);
        }
        a_sh[tid] = __ldg(&area[byte]);
    }
    __syncthreads();

    float S1 = 0.f, S2 = 0.f, Sq = 0.f, accB = 0.f;
    int t = blockIdx.x * K2_BLK + tid;
    if (t < TOTAL_B_THREADS) {
        int g = t % NGX;
        int rem = t / NGX;
        int yw = rem % NWIN_Y;
        int i = rem / NWIN_Y;
        int x0 = g * 8;

        int rA = (i * YP + yw) * XD;
        int rB = rA + XD;

        // ---- one load round: 8 columns (2 float4/row) + codes + carry ----
        const float4* pA = reinterpret_cast<const float4*>(g_E + rA + x0);
        const float4* pB = reinterpret_cast<const float4*>(g_E + rB + x0);
        float4 a0 = pA[0], a1 = pA[1];
        float4 b0 = pB[0], b1 = pB[1];
        uint2 za = *reinterpret_cast<const uint2*>(g_ZC + rA + x0);
        uint2 zb = *reinterpret_cast<const uint2*>(g_ZC + rB + x0);

        float Fp;
        unsigned cbp;
        if (x0 == 0) {
            Fp = 0.f;
            cbp = 0u;
        } else {
            int c = x0 - 1;
            float eAc = g_E[rA + c];
            float eBc = g_E[rB + c];
            unsigned zAc = g_ZC[rA + c];
            unsigned zBc = g_ZC[rB + c];
            Fp = eAc + eBc;
            cbp = zAc | (zBc << 1);
        }

#pragma unroll
        for (int j = 0; j < 2; j++) {
            float4 ea = j ? a1 : a0;
            float4 eb = j ? b1 : b0;
            // column codes for 4 columns: zc bytes <= 0x55 -> <<1 stays in-lane
            unsigned cw = (j ? za.y : za.x) | ((j ? zb.y : zb.x) << 1);
            // prevw byte k = code of column k-1 (byte0 = carry)
            unsigned prevw = __byte_perm(cw, cbp, 0x2104);
            // L byte k = lidx of window k ; P byte k = pidx of window k
            unsigned L = ((prevw << 4) & 0xF0F0F0F0u) | (cw & 0x0F0F0F0Fu);
            unsigned P = (prevw & 0xF0F0F0F0u) | ((cw >> 4) & 0x0F0F0F0Fu);

            float F0 = ea.x + eb.x;
            float F1 = ea.y + eb.y;
            float F2 = ea.z + eb.z;
            float F3 = ea.w + eb.w;

            float q0 = Fp + F0;
            float q1 = F0 + F1;
            float q2 = F1 + F2;
            float q3 = F2 + F3;

            float la0 = a_sh[L & 0xFFu];
            float la1 = a_sh[(L >> 8) & 0xFFu];
            float la2 = a_sh[(L >> 16) & 0xFFu];
            float la3 = a_sh[L >> 24];
            float pa0 = a_sh[P & 0xFFu];
            float pa1 = a_sh[(P >> 8) & 0xFFu];
            float pa2 = a_sh[(P >> 16) & 0xFFu];
            float pa3 = a_sh[P >> 24];

            Sq = fmaf(q0, la0, Sq);
            Sq = fmaf(q1, la1, Sq);
            Sq = fmaf(q2, la2, Sq);
            Sq = fmaf(q3, la3, Sq);
            S1 += (la0 + la1) + (la2 + la3);
            S2 += (pa0 + pa1) + (pa2 + pa3);

            // rare path: any window with label byte 0 or 255.
            // bce(byte==0) = sum softplus(p); bce(byte==255) = sum softplus(-p)
            // over the window's valid corners — precomputed pair-sums in g_S.
            unsigned r = __vcmpeq4(L, 0u) | __vcmpeq4(L, 0xFFFFFFFFu);
            if (r) {
#pragma unroll
                for (int k = 0; k < 4; k++) {
                    unsigned lb = (L >> (8 * k)) & 0xFFu;
                    if (lb == 0u || lb == 255u) {
                        int x = x0 + 4 * j + k;     // window; right col = x (<=383 here)
                        float2 sRA = g_S[rA + x];
                        float2 sRB = g_S[rB + x];
                        float s0 = sRA.x + sRB.x;
                        float s1 = sRA.y + sRB.y;
                        if (x > 0) {
                            float2 sLA = g_S[rA + x - 1];
                            float2 sLB = g_S[rB + x - 1];
                            s0 += sLA.x + sLB.x;
                            s1 += sLA.y + sLB.y;
                        }
                        accB += (lb == 255u) ? s1 : s0;
                    }
                }
            }

            Fp = F3;
            cbp = cw >> 24;
        }

        // group 47: edge window x=384 (right column is zero padding)
        if (g == NGX - 1) {
            float q = Fp;
            unsigned lidx = (cbp << 4) & 0xF0u;
            unsigned pidx = cbp & 0xF0u;
            float la = a_sh[lidx];
            float pa = a_sh[pidx];
            Sq = fmaf(q, la, Sq);
            S1 += la;
            S2 += pa;
            if (lidx == 0u) {   // lidx==255 impossible here (low nibble is 0)
                float2 sLA = g_S[rA + 383];
                float2 sLB = g_S[rB + 383];
                accB += sLA.x + sLB.x;
            }
        }
    }
    float accN = fmaf(Sq, -0.125f, S1);   // sum of (1 - q/8)*la
    float accD = S1 + S2;

    // deterministic warp-shuffle reduction
    accN = warp_sum(accN);
    accD = warp_sum(accD);
    accB = warp_sum(accB);
    int lane = tid & 31, warp = tid >> 5;
    if (lane == 0) { wN[warp] = accN; wD[warp] = accD; wB[warp] = accB; }
    __syncthreads();
    if (warp == 0) {
        float vN = lane < 8 ? wN[lane] : 0.f;
        float vD = lane < 8 ? wD[lane] : 0.f;
        float vB = lane < 8 ? wB[lane] : 0.f;
#pragma unroll
        for (int off = 4; off > 0; off >>= 1) {
            vN += __shfl_down_sync(0xffffffffu, vN, off);
            vD += __shfl_down_sync(0xffffffffu, vD, off);
            vB += __shfl_down_sync(0xffffffffu, vB, off);
        }
        if (lane == 0) {
            g_part[3 * blockIdx.x + 0] = vN;
            g_part[3 * blockIdx.x + 1] = vD;
            g_part[3 * blockIdx.x + 2] = vB;
        }
    }

    __threadfence();
    if (tid == 0) {
        unsigned prev = atomicAdd(&g_count, 1u);
        is_last = (prev == B_BLOCKS - 1);
    }
    __syncthreads();
    if (!is_last) return;

    double sN = 0.0, sD = 0.0, sB = 0.0;
    for (int b = tid; b < B_BLOCKS; b += K2_BLK) {
        sN += (double)g_part[3 * b + 0];
        sD += (double)g_part[3 * b + 1];
        sB += (double)g_part[3 * b + 2];
    }
    __shared__ double rd[K2_BLK];
    rd[tid] = sN; __syncthreads();
    for (int s = K2_BLK / 2; s > 0; s >>= 1) { if (tid < s) rd[tid] += rd[tid + s]; __syncthreads(); }
    double tN = rd[0]; __syncthreads();
    rd[tid] = sD; __syncthreads();
    for (int s = K2_BLK / 2; s > 0; s >>= 1) { if (tid < s) rd[tid] += rd[tid + s]; __syncthreads(); }
    double tD = rd[0]; __syncthreads();
    rd[tid] = sB; __syncthreads();
    for (int s = K2_BLK / 2; s > 0; s >>= 1) { if (tid < s) rd[tid] += rd[tid + s]; __syncthreads(); }
    double tB = rd[0];

    if (tid == 0) {
        double dice = 1.0 - (2.0 * tN + 1e-3) / (tD + 1e-3);
        double vol = tB / (8.0 * NP_WIN);
        out[0] = (float)(dice + vol);
    }
}

// ---------------------------------------------------------------------------
extern "C" void kernel_launch(void* const* d_in, const int* in_sizes, int n_in,
                              void* d_out, int out_size) {
    const float* pred   = (const float*)d_in[0];
    const int*   labels = (const int*)d_in[1];
    const float* area   = (const float*)d_in[2];

    k1<<<YD, XD>>>(pred, labels);
    k2<<<B_BLOCKS, K2_BLK>>>(pred, area, (float*)d_out);
}